// round 11
// baseline (speedup 1.0000x reference)
#include <cuda_runtime.h>
#include <cstdint>
#include <math.h>

#define NB 128
#define NTOK 577
#define NP 576
#define DD 768
#define NG 17
#define NGC 18          // 17 groups + cls row
#define NOCC 10

typedef unsigned long long ull;

// ---- packed f32x2 helpers (sm_103a) ----
__device__ __forceinline__ ull pk2(float a, float b) {
    ull r; asm("mov.b64 %0, {%1,%2};" : "=l"(r) : "f"(a), "f"(b)); return r;
}
__device__ __forceinline__ void fma2(ull &acc, ull a, ull b) {
    asm("fma.rn.f32x2 %0, %1, %2, %0;" : "+l"(acc) : "l"(a), "l"(b));
}
__device__ __forceinline__ float hadd2(ull a) {
    return __uint_as_float((unsigned)a) + __uint_as_float((unsigned)(a >> 32));
}
__device__ __forceinline__ void cpasync16(uint32_t dst, const void* src) {
    asm volatile("cp.async.cg.shared.global [%0], [%1], 16;"
                 :: "r"(dst), "l"(src) : "memory");
}

// scratch (device global; no allocation). Holds MASKED attn after K1.
__device__ float g_scores[(size_t)NB * NG * NP];

// ================= K1: scores + sim + topk + softmax + attn ===============
// (unchanged from R7 — proven)
#define K1_THREADS 576
#define TILE_D 32
#define NT (DD / TILE_D)            // 24
#define PITCH 36                    // floats/row: conflict-free LDS.128
#define TILE_FLOATS (32 * PITCH)    // 1152
#define WPITCH 772                  // W row pitch: 9*772*4 % 128 = 16 (bank-split)
#define OFF_W  (18 * 2 * TILE_FLOATS)          // 41472
#define OFF_CD (OFF_W + NGC * WPITCH)          // 55368
#define K1_SMEM_FLOATS (OFF_CD + NP)           // 55944 floats = 223776 B

extern __shared__ float sm1[];

__global__ void __launch_bounds__(K1_THREADS, 1)
k1_scores(const float* __restrict__ x, const float* __restrict__ gw,
          float* __restrict__ out) {
    const int b   = blockIdx.x;
    const int tid = threadIdx.x;
    const int w   = tid >> 5, ln = tid & 31;
    const int li  = ln & 15,  h  = ln >> 4;
    float* s_w  = sm1 + OFF_W;
    float* s_cd = sm1 + OFF_CD;

    const size_t xb = (size_t)b * NTOK * DD;

    for (int i = tid; i < DD * NG; i += K1_THREADS) {
        int d = i / NG, g = i % NG;
        s_w[g * WPITCH + d] = gw[i];
    }
    for (int i = tid; i < DD; i += K1_THREADS) s_w[NG * WPITCH + i] = x[xb + i];

    const uint32_t smem_base = (uint32_t)__cvta_generic_to_shared(sm1);
    const uint32_t buf0 = smem_base + (uint32_t)(w * 2) * TILE_FLOATS * 4;
    const uint32_t buf1 = buf0 + TILE_FLOATS * 4;
    const float* xrow = x + xb + DD + (size_t)(w * 32) * DD;

#pragma unroll
    for (int t = 0; t < 2; ++t) {
        uint32_t dst = t ? buf1 : buf0;
        const float* src = xrow + t * TILE_D;
#pragma unroll
        for (int k = 0; k < 8; ++k) {
            int idx = ln + 32 * k;
            int row = idx >> 3, ch = idx & 7;
            cpasync16(dst + (uint32_t)(row * PITCH + ch * 4) * 4,
                      src + (size_t)row * DD + ch * 4);
        }
        asm volatile("cp.async.commit_group;" ::: "memory");
    }
    __syncthreads();

    ull a0[9], a1[9], nr0 = 0, nr1 = 0;
#pragma unroll
    for (int g = 0; g < 9; ++g) { a0[g] = 0; a1[g] = 0; }

    const float* wbase = s_w + h * 9 * WPITCH;

    for (int t = 0; t < NT; ++t) {
        asm volatile("cp.async.wait_group 1;" ::: "memory");
        __syncwarp();
        const float* xt  = sm1 + (size_t)(w * 2 + (t & 1)) * TILE_FLOATS;
        const float* wd0 = wbase + t * TILE_D;
#pragma unroll
        for (int blk = 0; blk < 8; ++blk) {
            ulonglong2 xv0 = *reinterpret_cast<const ulonglong2*>(
                xt + li * PITCH + blk * 4);
            ulonglong2 xv1 = *reinterpret_cast<const ulonglong2*>(
                xt + (li + 16) * PITCH + blk * 4);
            const float* wdb = wd0 + blk * 4;
#pragma unroll
            for (int gi = 0; gi < 9; ++gi) {
                ulonglong2 wv = *reinterpret_cast<const ulonglong2*>(wdb + gi * WPITCH);
                fma2(a0[gi], xv0.x, wv.x); fma2(a0[gi], xv0.y, wv.y);
                fma2(a1[gi], xv1.x, wv.x); fma2(a1[gi], xv1.y, wv.y);
            }
            fma2(nr0, xv0.x, xv0.x); fma2(nr0, xv0.y, xv0.y);
            fma2(nr1, xv1.x, xv1.x); fma2(nr1, xv1.y, xv1.y);
        }
        __syncwarp();
        if (t + 2 < NT) {
            uint32_t dst = (t & 1) ? buf1 : buf0;
            const float* src = xrow + (t + 2) * TILE_D;
#pragma unroll
            for (int k = 0; k < 8; ++k) {
                int idx = ln + 32 * k;
                int row = idx >> 3, ch = idx & 7;
                cpasync16(dst + (uint32_t)(row * PITCH + ch * 4) * 4,
                          src + (size_t)row * DD + ch * 4);
            }
        }
        asm volatile("cp.async.commit_group;" ::: "memory");
    }

    // epilogue: scores -> smem (tile region dead)
    __syncthreads();
    float* s_sc   = sm1;
    float* s_sim  = sm1 + NG * NP;
    float* s_mask = s_sim + NP;

    const int p0 = w * 32 + li, p1 = p0 + 16;
#pragma unroll
    for (int gi = 0; gi < 9; ++gi) {
        int g = h * 9 + gi;
        float v0 = hadd2(a0[gi]), v1 = hadd2(a1[gi]);
        if (g < NG) {
            s_sc[g * NP + p0] = v0;
            s_sc[g * NP + p1] = v1;
        } else {
            s_cd[p0] = v0;
            s_cd[p1] = v1;
        }
    }
    __syncthreads();
    if (h == 0) {
        // cls-norm factor dropped: positive per-batch constant, ordering-invariant
        s_sim[p0] = s_cd[p0] / fmaxf(sqrtf(hadd2(nr0)), 1e-12f);
        s_sim[p1] = s_cd[p1] / fmaxf(sqrtf(hadd2(nr1)), 1e-12f);
        s_mask[p0] = 1.0f; s_mask[p1] = 1.0f;
    }
    __syncthreads();

    if (tid < 32) {
        for (int k = 0; k < NOCC; ++k) {
            float best = 3.4e38f; int bi = NP;
#pragma unroll
            for (int q = 0; q < NP / 32; ++q) {
                int idx = tid + q * 32;
                float v = s_sim[idx];
                if (v < best || (v == best && idx < bi)) { best = v; bi = idx; }
            }
#pragma unroll
            for (int off = 16; off; off >>= 1) {
                float ov = __shfl_down_sync(0xffffffffu, best, off);
                int   oi = __shfl_down_sync(0xffffffffu, bi, off);
                if (ov < best || (ov == best && oi < bi)) { best = ov; bi = oi; }
            }
            bi = __shfl_sync(0xffffffffu, bi, 0);
            if (tid == 0) { s_sim[bi] = 3.4e38f; s_mask[bi] = 0.0f; }
            __syncwarp();
        }
    }
    __syncthreads();

    {
        const int p = tid;
        const float mk = s_mask[p];
        float tv[NG];
        float m = -3.4e38f;
#pragma unroll
        for (int g = 0; g < NG; ++g) {
            tv[g] = s_sc[g * NP + p] * 10.0f;
            m = fmaxf(m, tv[g]);
        }
        float ssum = 0.f;
#pragma unroll
        for (int g = 0; g < NG; ++g) { tv[g] = __expf(tv[g] - m); ssum += tv[g]; }
        const float inv = 1.0f / ssum;
        float* oat = out + (size_t)NB * NGC * DD + (size_t)b * NG * NP;
#pragma unroll
        for (int g = 0; g < NG; ++g) {
            float a = tv[g] * inv;
            oat[g * NP + p] = (mk != 0.f) ? a : (1.0f / 17.0f);
            g_scores[((size_t)b * NG + g) * NP + p] = (mk != 0.f) ? a : 0.f;
        }
    }
}

// ======================= K3: group features + cls =========================
// grid (NB, 3), block 256, 3 CTAs/SM. Warp w owns 32 columns (warp-private
// cp.async double-buffered tiles [16p x 32c]). Lane li=ln&15 owns columns
// (2li, 2li+1); half h=ln>>4 computes groups [9h, 9h+9) (row 17 = zero pad).
#define K3_TP 16
#define K3_NT (NP / K3_TP)            // 36
#define WT_FLOATS (K3_TP * 32)        // 512 floats = 2 KB per buffer
#define K3_OFF_X (NGC * NP)           // 10368 (18 rows incl zero pad)
#define K3_SMEM_FLOATS (K3_OFF_X + 8 * 2 * WT_FLOATS)   // 18560 floats = 74240 B

extern __shared__ float sm3[];

__global__ void __launch_bounds__(256, 3)
k3_features(const float* __restrict__ x, float* __restrict__ out) {
    const int b   = blockIdx.x;
    const int tid = threadIdx.x;
    const int w   = tid >> 5, ln = tid & 31;
    const int li  = ln & 15,  h  = ln >> 4;
    float* s_at = sm3;
    float* wt0  = sm3 + K3_OFF_X + w * 2 * WT_FLOATS;

    const size_t xb = (size_t)b * NTOK * DD;
    const float* xsrc = x + xb + DD + blockIdx.y * 256 + w * 32;  // patch 0

    const uint32_t wt_base = (uint32_t)__cvta_generic_to_shared(wt0);

    // prologue: issue warp tiles 0,1
#pragma unroll
    for (int t = 0; t < 2; ++t) {
        uint32_t dst = wt_base + (uint32_t)t * WT_FLOATS * 4;
        const float* src = xsrc + (size_t)t * K3_TP * DD;
#pragma unroll
        for (int k = 0; k < 4; ++k) {
            int idx = ln + 32 * k;
            int row = idx >> 3, ch = idx & 7;
            cpasync16(dst + (uint32_t)(row * 32 + ch * 4) * 4,
                      src + (size_t)row * DD + ch * 4);
        }
        asm volatile("cp.async.commit_group;" ::: "memory");
    }

    // stage attn (17 rows) + zero pad row 17
    for (int i = tid; i < NG * NP; i += 256)
        s_at[i] = g_scores[(size_t)b * NG * NP + i];
    for (int i = tid; i < NP; i += 256)
        s_at[NG * NP + i] = 0.0f;
    __syncthreads();

    ull acc0[9], acc1[9];
#pragma unroll
    for (int g = 0; g < 9; ++g) { acc0[g] = 0; acc1[g] = 0; }

    const float* athalf = s_at + h * 9 * NP;

    for (int t = 0; t < K3_NT; ++t) {
        asm volatile("cp.async.wait_group 1;" ::: "memory");
        __syncwarp();
        const float* xt  = wt0 + (t & 1) * WT_FLOATS;
        const float* at0 = athalf + t * K3_TP;
#pragma unroll
        for (int q = 0; q < K3_TP / 4; ++q) {
            const float* xq = xt + 4 * q * 32 + 2 * li;
            float2 xa = *reinterpret_cast<const float2*>(xq + 0 * 32);
            float2 xb2 = *reinterpret_cast<const float2*>(xq + 1 * 32);
            float2 xc = *reinterpret_cast<const float2*>(xq + 2 * 32);
            float2 xd = *reinterpret_cast<const float2*>(xq + 3 * 32);
            ull x01c0 = pk2(xa.x, xb2.x), x23c0 = pk2(xc.x, xd.x);
            ull x01c1 = pk2(xa.y, xb2.y), x23c1 = pk2(xc.y, xd.y);
            const float* ap = at0 + 4 * q;
#pragma unroll
            for (int gi = 0; gi < 9; ++gi) {
                ulonglong2 at = *reinterpret_cast<const ulonglong2*>(ap + gi * NP);
                fma2(acc0[gi], x01c0, at.x); fma2(acc0[gi], x23c0, at.y);
                fma2(acc1[gi], x01c1, at.x); fma2(acc1[gi], x23c1, at.y);
            }
        }
        __syncwarp();
        if (t + 2 < K3_NT) {
            uint32_t dst = wt_base + (uint32_t)(t & 1) * WT_FLOATS * 4;
            const float* src = xsrc + (size_t)(t + 2) * K3_TP * DD;
#pragma unroll
            for (int k = 0; k < 4; ++k) {
                int idx = ln + 32 * k;
                int row = idx >> 3, ch = idx & 7;
                cpasync16(dst + (uint32_t)(row * 32 + ch * 4) * 4,
                          src + (size_t)row * DD + ch * 4);
            }
        }
        asm volatile("cp.async.commit_group;" ::: "memory");
    }

    const int d0 = blockIdx.y * 256 + w * 32 + 2 * li;
    float* ob = out + (size_t)b * NGC * DD;
    if (h == 0) {                              // cls row (once per column pair)
        ob[d0]     = x[xb + d0];
        ob[d0 + 1] = x[xb + d0 + 1];
    }
#pragma unroll
    for (int gi = 0; gi < 9; ++gi) {
        int g = h * 9 + gi;
        if (g < NG) {
            ob[(size_t)(1 + g) * DD + d0]     = hadd2(acc0[gi]);
            ob[(size_t)(1 + g) * DD + d0 + 1] = hadd2(acc1[gi]);
        }
    }
}

extern "C" void kernel_launch(void* const* d_in, const int* in_sizes, int n_in,
                              void* d_out, int out_size) {
    const float* x  = (const float*)d_in[0];
    const float* gw = (const float*)d_in[1];
    float* out = (float*)d_out;

    static bool inited = false;
    if (!inited) {
        cudaFuncSetAttribute(k1_scores, cudaFuncAttributeMaxDynamicSharedMemorySize,
                             K1_SMEM_FLOATS * 4);
        cudaFuncSetAttribute(k3_features, cudaFuncAttributeMaxDynamicSharedMemorySize,
                             K3_SMEM_FLOATS * 4);
        inited = true;
    }

    k1_scores<<<NB, K1_THREADS, K1_SMEM_FLOATS * 4>>>(x, gw, out);
    k3_features<<<dim3(NB, 3), 256, K3_SMEM_FLOATS * 4>>>(x, out);
}

// round 12
// speedup vs baseline: 1.0002x; 1.0002x over previous
#include <cuda_runtime.h>
#include <cstdint>
#include <math.h>

#define NB 128
#define NTOK 577
#define NP 576
#define DD 768
#define NG 17
#define NGC 18          // 17 groups + cls row
#define NOCC 10

typedef unsigned long long ull;

// ---- packed f32x2 helpers (sm_103a) ----
__device__ __forceinline__ ull pk2(float a, float b) {
    ull r; asm("mov.b64 %0, {%1,%2};" : "=l"(r) : "f"(a), "f"(b)); return r;
}
__device__ __forceinline__ void fma2(ull &acc, ull a, ull b) {
    asm("fma.rn.f32x2 %0, %1, %2, %0;" : "+l"(acc) : "l"(a), "l"(b));
}
__device__ __forceinline__ float hadd2(ull a) {
    return __uint_as_float((unsigned)a) + __uint_as_float((unsigned)(a >> 32));
}
__device__ __forceinline__ void cpasync16(uint32_t dst, const void* src) {
    asm volatile("cp.async.cg.shared.global [%0], [%1], 16;"
                 :: "r"(dst), "l"(src) : "memory");
}
__device__ __forceinline__ void cpasync4(uint32_t dst, const void* src) {
    asm volatile("cp.async.ca.shared.global [%0], [%1], 4;"
                 :: "r"(dst), "l"(src) : "memory");
}

// scratch (device global; no allocation). Holds MASKED attn after K1.
__device__ float g_scores[(size_t)NB * NG * NP];

// ================= K1: scores + sim + topk + softmax + attn ===============
// (unchanged from R7 — proven)
#define K1_THREADS 576
#define TILE_D 32
#define NT (DD / TILE_D)            // 24
#define PITCH 36                    // floats/row: conflict-free LDS.128
#define TILE_FLOATS (32 * PITCH)    // 1152
#define WPITCH 772                  // W row pitch: 9*772*4 % 128 = 16 (bank-split)
#define OFF_W  (18 * 2 * TILE_FLOATS)          // 41472
#define OFF_CD (OFF_W + NGC * WPITCH)          // 55368
#define K1_SMEM_FLOATS (OFF_CD + NP)           // 55944 floats = 223776 B

extern __shared__ float sm1[];

__global__ void __launch_bounds__(K1_THREADS, 1)
k1_scores(const float* __restrict__ x, const float* __restrict__ gw,
          float* __restrict__ out) {
    const int b   = blockIdx.x;
    const int tid = threadIdx.x;
    const int w   = tid >> 5, ln = tid & 31;
    const int li  = ln & 15,  h  = ln >> 4;
    float* s_w  = sm1 + OFF_W;
    float* s_cd = sm1 + OFF_CD;

    const size_t xb = (size_t)b * NTOK * DD;

    for (int i = tid; i < DD * NG; i += K1_THREADS) {
        int d = i / NG, g = i % NG;
        s_w[g * WPITCH + d] = gw[i];
    }
    for (int i = tid; i < DD; i += K1_THREADS) s_w[NG * WPITCH + i] = x[xb + i];

    const uint32_t smem_base = (uint32_t)__cvta_generic_to_shared(sm1);
    const uint32_t buf0 = smem_base + (uint32_t)(w * 2) * TILE_FLOATS * 4;
    const uint32_t buf1 = buf0 + TILE_FLOATS * 4;
    const float* xrow = x + xb + DD + (size_t)(w * 32) * DD;

#pragma unroll
    for (int t = 0; t < 2; ++t) {
        uint32_t dst = t ? buf1 : buf0;
        const float* src = xrow + t * TILE_D;
#pragma unroll
        for (int k = 0; k < 8; ++k) {
            int idx = ln + 32 * k;
            int row = idx >> 3, ch = idx & 7;
            cpasync16(dst + (uint32_t)(row * PITCH + ch * 4) * 4,
                      src + (size_t)row * DD + ch * 4);
        }
        asm volatile("cp.async.commit_group;" ::: "memory");
    }
    __syncthreads();

    ull a0[9], a1[9], nr0 = 0, nr1 = 0;
#pragma unroll
    for (int g = 0; g < 9; ++g) { a0[g] = 0; a1[g] = 0; }

    const float* wbase = s_w + h * 9 * WPITCH;

    for (int t = 0; t < NT; ++t) {
        asm volatile("cp.async.wait_group 1;" ::: "memory");
        __syncwarp();
        const float* xt  = sm1 + (size_t)(w * 2 + (t & 1)) * TILE_FLOATS;
        const float* wd0 = wbase + t * TILE_D;
#pragma unroll
        for (int blk = 0; blk < 8; ++blk) {
            ulonglong2 xv0 = *reinterpret_cast<const ulonglong2*>(
                xt + li * PITCH + blk * 4);
            ulonglong2 xv1 = *reinterpret_cast<const ulonglong2*>(
                xt + (li + 16) * PITCH + blk * 4);
            const float* wdb = wd0 + blk * 4;
#pragma unroll
            for (int gi = 0; gi < 9; ++gi) {
                ulonglong2 wv = *reinterpret_cast<const ulonglong2*>(wdb + gi * WPITCH);
                fma2(a0[gi], xv0.x, wv.x); fma2(a0[gi], xv0.y, wv.y);
                fma2(a1[gi], xv1.x, wv.x); fma2(a1[gi], xv1.y, wv.y);
            }
            fma2(nr0, xv0.x, xv0.x); fma2(nr0, xv0.y, xv0.y);
            fma2(nr1, xv1.x, xv1.x); fma2(nr1, xv1.y, xv1.y);
        }
        __syncwarp();
        if (t + 2 < NT) {
            uint32_t dst = (t & 1) ? buf1 : buf0;
            const float* src = xrow + (t + 2) * TILE_D;
#pragma unroll
            for (int k = 0; k < 8; ++k) {
                int idx = ln + 32 * k;
                int row = idx >> 3, ch = idx & 7;
                cpasync16(dst + (uint32_t)(row * PITCH + ch * 4) * 4,
                          src + (size_t)row * DD + ch * 4);
            }
        }
        asm volatile("cp.async.commit_group;" ::: "memory");
    }

    // epilogue: scores -> smem (tile region dead)
    __syncthreads();
    float* s_sc   = sm1;
    float* s_sim  = sm1 + NG * NP;
    float* s_mask = s_sim + NP;

    const int p0 = w * 32 + li, p1 = p0 + 16;
#pragma unroll
    for (int gi = 0; gi < 9; ++gi) {
        int g = h * 9 + gi;
        float v0 = hadd2(a0[gi]), v1 = hadd2(a1[gi]);
        if (g < NG) {
            s_sc[g * NP + p0] = v0;
            s_sc[g * NP + p1] = v1;
        } else {
            s_cd[p0] = v0;
            s_cd[p1] = v1;
        }
    }
    __syncthreads();
    if (h == 0) {
        // cls-norm factor dropped: positive per-batch constant, ordering-invariant
        s_sim[p0] = s_cd[p0] / fmaxf(sqrtf(hadd2(nr0)), 1e-12f);
        s_sim[p1] = s_cd[p1] / fmaxf(sqrtf(hadd2(nr1)), 1e-12f);
        s_mask[p0] = 1.0f; s_mask[p1] = 1.0f;
    }
    __syncthreads();

    if (tid < 32) {
        for (int k = 0; k < NOCC; ++k) {
            float best = 3.4e38f; int bi = NP;
#pragma unroll
            for (int q = 0; q < NP / 32; ++q) {
                int idx = tid + q * 32;
                float v = s_sim[idx];
                if (v < best || (v == best && idx < bi)) { best = v; bi = idx; }
            }
#pragma unroll
            for (int off = 16; off; off >>= 1) {
                float ov = __shfl_down_sync(0xffffffffu, best, off);
                int   oi = __shfl_down_sync(0xffffffffu, bi, off);
                if (ov < best || (ov == best && oi < bi)) { best = ov; bi = oi; }
            }
            bi = __shfl_sync(0xffffffffu, bi, 0);
            if (tid == 0) { s_sim[bi] = 3.4e38f; s_mask[bi] = 0.0f; }
            __syncwarp();
        }
    }
    __syncthreads();

    {
        const int p = tid;
        const float mk = s_mask[p];
        float tv[NG];
        float m = -3.4e38f;
#pragma unroll
        for (int g = 0; g < NG; ++g) {
            tv[g] = s_sc[g * NP + p] * 10.0f;
            m = fmaxf(m, tv[g]);
        }
        float ssum = 0.f;
#pragma unroll
        for (int g = 0; g < NG; ++g) { tv[g] = __expf(tv[g] - m); ssum += tv[g]; }
        const float inv = 1.0f / ssum;
        float* oat = out + (size_t)NB * NGC * DD + (size_t)b * NG * NP;
#pragma unroll
        for (int g = 0; g < NG; ++g) {
            float a = tv[g] * inv;
            oat[g * NP + p] = (mk != 0.f) ? a : (1.0f / 17.0f);
            g_scores[((size_t)b * NG + g) * NP + p] = (mk != 0.f) ? a : 0.f;
        }
    }
}

// ======================= K3: group features + cls =========================
// grid (NB, 3), block 256, 3 CTAs/SM. Warp w owns 32 columns.
// x tiles stored COLUMN-MAJOR via 4B cp.async (transpose in the copy):
// xs[col*12 + patch], 8 patches/tile -> LDS.128 yields 4 consecutive patches
// of one column, feeding fma2 with ZERO packing MOVs.
// Lane li=ln&15 owns cols (li, li+16); half h computes groups [8h, 8h+9)
// (g8 overlap, written by h=0 only).
#define K3_TP 8
#define K3_NT (NP / K3_TP)            // 72
#define CSTR 12                       // column stride in floats
#define WT_FLOATS (32 * CSTR)         // 384 floats = 1536 B per buffer
#define AT_HB (9 * NP + 4)            // half-block stride (bank-shifted by 4)
#define K3_OFF_X (2 * 9 * NP + 4)     // 10372 (rows 0-8 | pad | rows 8-16)
#define K3_SMEM_FLOATS (K3_OFF_X + 8 * 2 * WT_FLOATS)   // 16516 fl = 66064 B

extern __shared__ float sm3[];

__global__ void __launch_bounds__(256, 3)
k3_features(const float* __restrict__ x, float* __restrict__ out) {
    const int b   = blockIdx.x;
    const int tid = threadIdx.x;
    const int w   = tid >> 5, ln = tid & 31;
    const int li  = ln & 15,  h  = ln >> 4;
    float* s_at = sm3;
    float* wt0  = sm3 + K3_OFF_X + w * 2 * WT_FLOATS;

    const size_t xb = (size_t)b * NTOK * DD;
    const float* xsrc = x + xb + DD + blockIdx.y * 256 + w * 32;  // patch 0

    const uint32_t wt_base = (uint32_t)__cvta_generic_to_shared(wt0);

    // prologue: issue tiles 0,1 (8 x 4B cp.async per lane; gmem coalesced,
    // smem scattered column-major)
#pragma unroll
    for (int t = 0; t < 2; ++t) {
        uint32_t dst = wt_base + (uint32_t)t * WT_FLOATS * 4;
        const float* src = xsrc + (size_t)t * K3_TP * DD + ln;
#pragma unroll
        for (int p = 0; p < K3_TP; ++p)
            cpasync4(dst + (uint32_t)(ln * CSTR + p) * 4, src + (size_t)p * DD);
        asm volatile("cp.async.commit_group;" ::: "memory");
    }

    // stage masked attn: rows 0-8 at [0), rows 8-16 at [AT_HB) (row 8 dup)
    for (int i = tid; i < 2 * 9 * NP; i += 256) {
        int half = i / (9 * NP), j = i - half * (9 * NP);
        int g = half * 8 + j / NP;
        s_at[half * AT_HB + j] = g_scores[(size_t)b * NG * NP + (size_t)g * NP + (j % NP)];
    }
    __syncthreads();

    ull acc0[9], acc1[9];
#pragma unroll
    for (int g = 0; g < 9; ++g) { acc0[g] = 0; acc1[g] = 0; }

    const float* athalf = s_at + h * AT_HB;

    for (int t = 0; t < K3_NT; ++t) {
        asm volatile("cp.async.wait_group 1;" ::: "memory");
        __syncwarp();
        const float* xt = wt0 + (t & 1) * WT_FLOATS;
        const float* atp = athalf + t * K3_TP;
#pragma unroll
        for (int q = 0; q < K3_TP / 4; ++q) {     // q = 0,1
            ulonglong2 xc0 = *reinterpret_cast<const ulonglong2*>(
                xt + li * CSTR + 4 * q);
            ulonglong2 xc1 = *reinterpret_cast<const ulonglong2*>(
                xt + (li + 16) * CSTR + 4 * q);
            const float* ap = atp + 4 * q;
#pragma unroll
            for (int gi = 0; gi < 9; ++gi) {
                ulonglong2 at = *reinterpret_cast<const ulonglong2*>(ap + gi * NP);
                fma2(acc0[gi], xc0.x, at.x); fma2(acc0[gi], xc0.y, at.y);
                fma2(acc1[gi], xc1.x, at.x); fma2(acc1[gi], xc1.y, at.y);
            }
        }
        __syncwarp();
        if (t + 2 < K3_NT) {
            uint32_t dst = wt_base + (uint32_t)(t & 1) * WT_FLOATS * 4;
            const float* src = xsrc + (size_t)(t + 2) * K3_TP * DD + ln;
#pragma unroll
            for (int p = 0; p < K3_TP; ++p)
                cpasync4(dst + (uint32_t)(ln * CSTR + p) * 4, src + (size_t)p * DD);
        }
        asm volatile("cp.async.commit_group;" ::: "memory");
    }

    const int d0 = blockIdx.y * 256 + w * 32 + li, d1 = d0 + 16;
    float* ob = out + (size_t)b * NGC * DD;
    if (h == 0) {                              // cls row + g8 owned by h=0
        ob[d0] = x[xb + d0];
        ob[d1] = x[xb + d1];
#pragma unroll
        for (int gi = 0; gi < 9; ++gi) {       // groups 0..8
            ob[(size_t)(1 + gi) * DD + d0] = hadd2(acc0[gi]);
            ob[(size_t)(1 + gi) * DD + d1] = hadd2(acc1[gi]);
        }
    } else {
#pragma unroll
        for (int gi = 1; gi < 9; ++gi) {       // groups 9..16 (skip dup g8)
            ob[(size_t)(1 + 8 + gi) * DD + d0] = hadd2(acc0[gi]);
            ob[(size_t)(1 + 8 + gi) * DD + d1] = hadd2(acc1[gi]);
        }
    }
}

extern "C" void kernel_launch(void* const* d_in, const int* in_sizes, int n_in,
                              void* d_out, int out_size) {
    const float* x  = (const float*)d_in[0];
    const float* gw = (const float*)d_in[1];
    float* out = (float*)d_out;

    static bool inited = false;
    if (!inited) {
        cudaFuncSetAttribute(k1_scores, cudaFuncAttributeMaxDynamicSharedMemorySize,
                             K1_SMEM_FLOATS * 4);
        cudaFuncSetAttribute(k3_features, cudaFuncAttributeMaxDynamicSharedMemorySize,
                             K3_SMEM_FLOATS * 4);
        inited = true;
    }

    k1_scores<<<NB, K1_THREADS, K1_SMEM_FLOATS * 4>>>(x, gw, out);
    k3_features<<<dim3(NB, 3), 256, K3_SMEM_FLOATS * 4>>>(x, out);
}

// round 13
// speedup vs baseline: 1.0015x; 1.0013x over previous
#include <cuda_runtime.h>
#include <cstdint>
#include <math.h>

#define NB 128
#define NTOK 577
#define NP 576
#define DD 768
#define NG 17
#define NGC 18          // 17 groups + cls row
#define NOCC 10

typedef unsigned long long ull;

// ---- packed f32x2 helpers (sm_103a) ----
__device__ __forceinline__ ull pk2(float a, float b) {
    ull r; asm("mov.b64 %0, {%1,%2};" : "=l"(r) : "f"(a), "f"(b)); return r;
}
__device__ __forceinline__ void fma2(ull &acc, ull a, ull b) {
    asm("fma.rn.f32x2 %0, %1, %2, %0;" : "+l"(acc) : "l"(a), "l"(b));
}
__device__ __forceinline__ float hadd2(ull a) {
    return __uint_as_float((unsigned)a) + __uint_as_float((unsigned)(a >> 32));
}
__device__ __forceinline__ void cpasync16(uint32_t dst, const void* src) {
    asm volatile("cp.async.cg.shared.global [%0], [%1], 16;"
                 :: "r"(dst), "l"(src) : "memory");
}

// scratch (device global; no allocation). Holds MASKED attn after K1.
__device__ float g_scores[(size_t)NB * NG * NP];

// ================= K1: scores + sim + topk + softmax + attn ===============
// (unchanged from R7 — proven)
#define K1_THREADS 576
#define TILE_D 32
#define NT (DD / TILE_D)            // 24
#define PITCH 36                    // floats/row: conflict-free LDS.128
#define TILE_FLOATS (32 * PITCH)    // 1152
#define WPITCH 772                  // W row pitch: 9*772*4 % 128 = 16 (bank-split)
#define OFF_W  (18 * 2 * TILE_FLOATS)          // 41472
#define OFF_CD (OFF_W + NGC * WPITCH)          // 55368
#define K1_SMEM_FLOATS (OFF_CD + NP)           // 55944 floats = 223776 B

extern __shared__ float sm1[];

__global__ void __launch_bounds__(K1_THREADS, 1)
k1_scores(const float* __restrict__ x, const float* __restrict__ gw,
          float* __restrict__ out) {
    const int b   = blockIdx.x;
    const int tid = threadIdx.x;
    const int w   = tid >> 5, ln = tid & 31;
    const int li  = ln & 15,  h  = ln >> 4;
    float* s_w  = sm1 + OFF_W;
    float* s_cd = sm1 + OFF_CD;

    const size_t xb = (size_t)b * NTOK * DD;

    for (int i = tid; i < DD * NG; i += K1_THREADS) {
        int d = i / NG, g = i % NG;
        s_w[g * WPITCH + d] = gw[i];
    }
    for (int i = tid; i < DD; i += K1_THREADS) s_w[NG * WPITCH + i] = x[xb + i];

    const uint32_t smem_base = (uint32_t)__cvta_generic_to_shared(sm1);
    const uint32_t buf0 = smem_base + (uint32_t)(w * 2) * TILE_FLOATS * 4;
    const uint32_t buf1 = buf0 + TILE_FLOATS * 4;
    const float* xrow = x + xb + DD + (size_t)(w * 32) * DD;

#pragma unroll
    for (int t = 0; t < 2; ++t) {
        uint32_t dst = t ? buf1 : buf0;
        const float* src = xrow + t * TILE_D;
#pragma unroll
        for (int k = 0; k < 8; ++k) {
            int idx = ln + 32 * k;
            int row = idx >> 3, ch = idx & 7;
            cpasync16(dst + (uint32_t)(row * PITCH + ch * 4) * 4,
                      src + (size_t)row * DD + ch * 4);
        }
        asm volatile("cp.async.commit_group;" ::: "memory");
    }
    __syncthreads();

    ull a0[9], a1[9], nr0 = 0, nr1 = 0;
#pragma unroll
    for (int g = 0; g < 9; ++g) { a0[g] = 0; a1[g] = 0; }

    const float* wbase = s_w + h * 9 * WPITCH;

    for (int t = 0; t < NT; ++t) {
        asm volatile("cp.async.wait_group 1;" ::: "memory");
        __syncwarp();
        const float* xt  = sm1 + (size_t)(w * 2 + (t & 1)) * TILE_FLOATS;
        const float* wd0 = wbase + t * TILE_D;
#pragma unroll
        for (int blk = 0; blk < 8; ++blk) {
            ulonglong2 xv0 = *reinterpret_cast<const ulonglong2*>(
                xt + li * PITCH + blk * 4);
            ulonglong2 xv1 = *reinterpret_cast<const ulonglong2*>(
                xt + (li + 16) * PITCH + blk * 4);
            const float* wdb = wd0 + blk * 4;
#pragma unroll
            for (int gi = 0; gi < 9; ++gi) {
                ulonglong2 wv = *reinterpret_cast<const ulonglong2*>(wdb + gi * WPITCH);
                fma2(a0[gi], xv0.x, wv.x); fma2(a0[gi], xv0.y, wv.y);
                fma2(a1[gi], xv1.x, wv.x); fma2(a1[gi], xv1.y, wv.y);
            }
            fma2(nr0, xv0.x, xv0.x); fma2(nr0, xv0.y, xv0.y);
            fma2(nr1, xv1.x, xv1.x); fma2(nr1, xv1.y, xv1.y);
        }
        __syncwarp();
        if (t + 2 < NT) {
            uint32_t dst = (t & 1) ? buf1 : buf0;
            const float* src = xrow + (t + 2) * TILE_D;
#pragma unroll
            for (int k = 0; k < 8; ++k) {
                int idx = ln + 32 * k;
                int row = idx >> 3, ch = idx & 7;
                cpasync16(dst + (uint32_t)(row * PITCH + ch * 4) * 4,
                          src + (size_t)row * DD + ch * 4);
            }
        }
        asm volatile("cp.async.commit_group;" ::: "memory");
    }

    // epilogue: scores -> smem (tile region dead)
    __syncthreads();
    float* s_sc   = sm1;
    float* s_sim  = sm1 + NG * NP;
    float* s_mask = s_sim + NP;

    const int p0 = w * 32 + li, p1 = p0 + 16;
#pragma unroll
    for (int gi = 0; gi < 9; ++gi) {
        int g = h * 9 + gi;
        float v0 = hadd2(a0[gi]), v1 = hadd2(a1[gi]);
        if (g < NG) {
            s_sc[g * NP + p0] = v0;
            s_sc[g * NP + p1] = v1;
        } else {
            s_cd[p0] = v0;
            s_cd[p1] = v1;
        }
    }
    __syncthreads();
    if (h == 0) {
        // cls-norm factor dropped: positive per-batch constant, ordering-invariant
        s_sim[p0] = s_cd[p0] / fmaxf(sqrtf(hadd2(nr0)), 1e-12f);
        s_sim[p1] = s_cd[p1] / fmaxf(sqrtf(hadd2(nr1)), 1e-12f);
        s_mask[p0] = 1.0f; s_mask[p1] = 1.0f;
    }
    __syncthreads();

    if (tid < 32) {
        for (int k = 0; k < NOCC; ++k) {
            float best = 3.4e38f; int bi = NP;
#pragma unroll
            for (int q = 0; q < NP / 32; ++q) {
                int idx = tid + q * 32;
                float v = s_sim[idx];
                if (v < best || (v == best && idx < bi)) { best = v; bi = idx; }
            }
#pragma unroll
            for (int off = 16; off; off >>= 1) {
                float ov = __shfl_down_sync(0xffffffffu, best, off);
                int   oi = __shfl_down_sync(0xffffffffu, bi, off);
                if (ov < best || (ov == best && oi < bi)) { best = ov; bi = oi; }
            }
            bi = __shfl_sync(0xffffffffu, bi, 0);
            if (tid == 0) { s_sim[bi] = 3.4e38f; s_mask[bi] = 0.0f; }
            __syncwarp();
        }
    }
    __syncthreads();

    {
        const int p = tid;
        const float mk = s_mask[p];
        float tv[NG];
        float m = -3.4e38f;
#pragma unroll
        for (int g = 0; g < NG; ++g) {
            tv[g] = s_sc[g * NP + p] * 10.0f;
            m = fmaxf(m, tv[g]);
        }
        float ssum = 0.f;
#pragma unroll
        for (int g = 0; g < NG; ++g) { tv[g] = __expf(tv[g] - m); ssum += tv[g]; }
        const float inv = 1.0f / ssum;
        float* oat = out + (size_t)NB * NGC * DD + (size_t)b * NG * NP;
#pragma unroll
        for (int g = 0; g < NG; ++g) {
            float a = tv[g] * inv;
            oat[g * NP + p] = (mk != 0.f) ? a : (1.0f / 17.0f);
            g_scores[((size_t)b * NG + g) * NP + p] = (mk != 0.f) ? a : 0.f;
        }
    }
}

// ======================= K3: group features + cls =========================
// grid (NB, 3), block 512 (16 warps), 2 CTAs/SM. Patch-split: warps 0-7
// accumulate patches [0,288), warps 8-15 patches [288,576); warp w&7 owns
// columns [32(w&7), +32). R10's warp-private cp.async double-buffer pipeline,
// 18 tiles per half. Partials merged via each warp's own (dead) tile buffer.
#define K3_THREADS 512
#define K3_TP 16
#define K3_NTH 18                     // tiles per half (288/16)
#define WT_FLOATS (K3_TP * 32)        // 512 floats = 2 KB per buffer
#define K3_OFF_X (NG * NP)            // 9792
#define K3_SMEM_FLOATS (K3_OFF_X + 16 * 2 * WT_FLOATS)  // 26176 fl = 104704 B

extern __shared__ float sm3[];

__global__ void __launch_bounds__(K3_THREADS, 2)
k3_features(const float* __restrict__ x, float* __restrict__ out) {
    const int b   = blockIdx.x;
    const int tid = threadIdx.x;
    const int w   = tid >> 5, ln = tid & 31;
    const int hh  = w >> 3;           // patch half: 0 or 1
    const int ww  = w & 7;            // column-warp within half
    const int d   = blockIdx.y * 256 + ww * 32 + ln;
    float* s_at = sm3;
    float* wt0  = sm3 + K3_OFF_X + w * 2 * WT_FLOATS;

    const size_t xb = (size_t)b * NTOK * DD;
    // this warp's slice: patch base hh*288, column base
    const float* xsrc = x + xb + DD + (size_t)(hh * 288) * DD
                        + blockIdx.y * 256 + ww * 32;

    const uint32_t wt_base = (uint32_t)__cvta_generic_to_shared(wt0);

    // prologue: issue warp tiles 0,1
#pragma unroll
    for (int t = 0; t < 2; ++t) {
        uint32_t dst = wt_base + (uint32_t)t * WT_FLOATS * 4;
        const float* src = xsrc + (size_t)t * K3_TP * DD;
#pragma unroll
        for (int k = 0; k < 4; ++k) {
            int idx = ln + 32 * k;
            int row = idx >> 3, ch = idx & 7;
            cpasync16(dst + (uint32_t)(row * 32 + ch * 4) * 4,
                      src + (size_t)row * DD + ch * 4);
        }
        asm volatile("cp.async.commit_group;" ::: "memory");
    }

    // stage attn cooperatively
    for (int i = tid; i < NG * NP; i += K3_THREADS)
        s_at[i] = g_scores[(size_t)b * NG * NP + i];
    __syncthreads();   // attn visible to all warps

    ull acc[NG];
#pragma unroll
    for (int g = 0; g < NG; ++g) acc[g] = 0ull;

    const float* athalf = s_at + hh * 288;   // this half's patch window

    for (int t = 0; t < K3_NTH; ++t) {
        asm volatile("cp.async.wait_group 1;" ::: "memory");
        __syncwarp();
        const float* xt  = wt0 + (t & 1) * WT_FLOATS;
        const float* at0 = athalf + t * K3_TP;
#pragma unroll
        for (int q = 0; q < K3_TP / 4; ++q) {
            float c0 = xt[(4 * q + 0) * 32 + ln];
            float c1 = xt[(4 * q + 1) * 32 + ln];
            float c2 = xt[(4 * q + 2) * 32 + ln];
            float c3 = xt[(4 * q + 3) * 32 + ln];
            ull x01 = pk2(c0, c1), x23 = pk2(c2, c3);
            const float* ap = at0 + 4 * q;
#pragma unroll
            for (int g = 0; g < NG; ++g) {
                ulonglong2 at = *reinterpret_cast<const ulonglong2*>(ap + g * NP);
                fma2(acc[g], x01, at.x);
                fma2(acc[g], x23, at.y);
            }
        }
        __syncwarp();
        if (t + 2 < K3_NTH) {
            uint32_t dst = wt_base + (uint32_t)(t & 1) * WT_FLOATS * 4;
            const float* src = xsrc + (size_t)(t + 2) * K3_TP * DD;
#pragma unroll
            for (int k = 0; k < 4; ++k) {
                int idx = ln + 32 * k;
                int row = idx >> 3, ch = idx & 7;
                cpasync16(dst + (uint32_t)(row * 32 + ch * 4) * 4,
                          src + (size_t)row * DD + ch * 4);
            }
        }
        asm volatile("cp.async.commit_group;" ::: "memory");
    }

    // drain copies, then merge halves through hh=1 warps' own tile buffers
    asm volatile("cp.async.wait_group 0;" ::: "memory");
    __syncwarp();
    if (hh == 1) {
#pragma unroll
        for (int g = 0; g < NG; ++g)
            wt0[ln * NG + g] = hadd2(acc[g]);     // 544 floats, own buffer
    }
    __syncthreads();
    if (hh == 0) {
        const float* partner = sm3 + K3_OFF_X + (w + 8) * 2 * WT_FLOATS;
        float* ob = out + (size_t)b * NGC * DD;
        ob[d] = x[xb + d];                        // feats[b][0][d] = cls
#pragma unroll
        for (int g = 0; g < NG; ++g)
            ob[(size_t)(1 + g) * DD + d] = hadd2(acc[g]) + partner[ln * NG + g];
    }
}

extern "C" void kernel_launch(void* const* d_in, const int* in_sizes, int n_in,
                              void* d_out, int out_size) {
    const float* x  = (const float*)d_in[0];
    const float* gw = (const float*)d_in[1];
    float* out = (float*)d_out;

    static bool inited = false;
    if (!inited) {
        cudaFuncSetAttribute(k1_scores, cudaFuncAttributeMaxDynamicSharedMemorySize,
                             K1_SMEM_FLOATS * 4);
        cudaFuncSetAttribute(k3_features, cudaFuncAttributeMaxDynamicSharedMemorySize,
                             K3_SMEM_FLOATS * 4);
        inited = true;
    }

    k1_scores<<<NB, K1_THREADS, K1_SMEM_FLOATS * 4>>>(x, gw, out);
    k3_features<<<dim3(NB, 3), K3_THREADS, K3_SMEM_FLOATS * 4>>>(x, out);
}

// round 14
// speedup vs baseline: 1.1227x; 1.1210x over previous
#include <cuda_runtime.h>
#include <cstdint>
#include <math.h>

#define NB 128
#define NTOK 577
#define NP 576
#define DD 768
#define NG 17
#define NGC 18          // 17 groups + cls row
#define NOCC 10

typedef unsigned long long ull;

// ---- packed f32x2 helpers (sm_103a) ----
__device__ __forceinline__ ull pk2(float a, float b) {
    ull r; asm("mov.b64 %0, {%1,%2};" : "=l"(r) : "f"(a), "f"(b)); return r;
}
__device__ __forceinline__ void fma2(ull &acc, ull a, ull b) {
    asm("fma.rn.f32x2 %0, %1, %2, %0;" : "+l"(acc) : "l"(a), "l"(b));
}
__device__ __forceinline__ float hadd2(ull a) {
    return __uint_as_float((unsigned)a) + __uint_as_float((unsigned)(a >> 32));
}
__device__ __forceinline__ void cpasync16(uint32_t dst, const void* src) {
    asm volatile("cp.async.cg.shared.global [%0], [%1], 16;"
                 :: "r"(dst), "l"(src) : "memory");
}

// scratch (device global; no allocation). Holds MASKED attn after K1.
__device__ float g_scores[(size_t)NB * NG * NP];

// ================= K1: scores + sim + topk + softmax + attn ===============
// (unchanged from R7 — proven)
#define K1_THREADS 576
#define TILE_D 32
#define NT (DD / TILE_D)            // 24
#define PITCH 36                    // floats/row: conflict-free LDS.128
#define TILE_FLOATS (32 * PITCH)    // 1152
#define WPITCH 772                  // W row pitch: 9*772*4 % 128 = 16 (bank-split)
#define OFF_W  (18 * 2 * TILE_FLOATS)          // 41472
#define OFF_CD (OFF_W + NGC * WPITCH)          // 55368
#define K1_SMEM_FLOATS (OFF_CD + NP)           // 55944 floats = 223776 B

extern __shared__ float sm1[];

__global__ void __launch_bounds__(K1_THREADS, 1)
k1_scores(const float* __restrict__ x, const float* __restrict__ gw,
          float* __restrict__ out) {
    const int b   = blockIdx.x;
    const int tid = threadIdx.x;
    const int w   = tid >> 5, ln = tid & 31;
    const int li  = ln & 15,  h  = ln >> 4;
    float* s_w  = sm1 + OFF_W;
    float* s_cd = sm1 + OFF_CD;

    const size_t xb = (size_t)b * NTOK * DD;

    for (int i = tid; i < DD * NG; i += K1_THREADS) {
        int d = i / NG, g = i % NG;
        s_w[g * WPITCH + d] = gw[i];
    }
    for (int i = tid; i < DD; i += K1_THREADS) s_w[NG * WPITCH + i] = x[xb + i];

    const uint32_t smem_base = (uint32_t)__cvta_generic_to_shared(sm1);
    const uint32_t buf0 = smem_base + (uint32_t)(w * 2) * TILE_FLOATS * 4;
    const uint32_t buf1 = buf0 + TILE_FLOATS * 4;
    const float* xrow = x + xb + DD + (size_t)(w * 32) * DD;

#pragma unroll
    for (int t = 0; t < 2; ++t) {
        uint32_t dst = t ? buf1 : buf0;
        const float* src = xrow + t * TILE_D;
#pragma unroll
        for (int k = 0; k < 8; ++k) {
            int idx = ln + 32 * k;
            int row = idx >> 3, ch = idx & 7;
            cpasync16(dst + (uint32_t)(row * PITCH + ch * 4) * 4,
                      src + (size_t)row * DD + ch * 4);
        }
        asm volatile("cp.async.commit_group;" ::: "memory");
    }
    __syncthreads();

    ull a0[9], a1[9], nr0 = 0, nr1 = 0;
#pragma unroll
    for (int g = 0; g < 9; ++g) { a0[g] = 0; a1[g] = 0; }

    const float* wbase = s_w + h * 9 * WPITCH;

    for (int t = 0; t < NT; ++t) {
        asm volatile("cp.async.wait_group 1;" ::: "memory");
        __syncwarp();
        const float* xt  = sm1 + (size_t)(w * 2 + (t & 1)) * TILE_FLOATS;
        const float* wd0 = wbase + t * TILE_D;
#pragma unroll
        for (int blk = 0; blk < 8; ++blk) {
            ulonglong2 xv0 = *reinterpret_cast<const ulonglong2*>(
                xt + li * PITCH + blk * 4);
            ulonglong2 xv1 = *reinterpret_cast<const ulonglong2*>(
                xt + (li + 16) * PITCH + blk * 4);
            const float* wdb = wd0 + blk * 4;
#pragma unroll
            for (int gi = 0; gi < 9; ++gi) {
                ulonglong2 wv = *reinterpret_cast<const ulonglong2*>(wdb + gi * WPITCH);
                fma2(a0[gi], xv0.x, wv.x); fma2(a0[gi], xv0.y, wv.y);
                fma2(a1[gi], xv1.x, wv.x); fma2(a1[gi], xv1.y, wv.y);
            }
            fma2(nr0, xv0.x, xv0.x); fma2(nr0, xv0.y, xv0.y);
            fma2(nr1, xv1.x, xv1.x); fma2(nr1, xv1.y, xv1.y);
        }
        __syncwarp();
        if (t + 2 < NT) {
            uint32_t dst = (t & 1) ? buf1 : buf0;
            const float* src = xrow + (t + 2) * TILE_D;
#pragma unroll
            for (int k = 0; k < 8; ++k) {
                int idx = ln + 32 * k;
                int row = idx >> 3, ch = idx & 7;
                cpasync16(dst + (uint32_t)(row * PITCH + ch * 4) * 4,
                          src + (size_t)row * DD + ch * 4);
            }
        }
        asm volatile("cp.async.commit_group;" ::: "memory");
    }

    // epilogue: scores -> smem (tile region dead)
    __syncthreads();
    float* s_sc   = sm1;
    float* s_sim  = sm1 + NG * NP;
    float* s_mask = s_sim + NP;

    const int p0 = w * 32 + li, p1 = p0 + 16;
#pragma unroll
    for (int gi = 0; gi < 9; ++gi) {
        int g = h * 9 + gi;
        float v0 = hadd2(a0[gi]), v1 = hadd2(a1[gi]);
        if (g < NG) {
            s_sc[g * NP + p0] = v0;
            s_sc[g * NP + p1] = v1;
        } else {
            s_cd[p0] = v0;
            s_cd[p1] = v1;
        }
    }
    __syncthreads();
    if (h == 0) {
        // cls-norm factor dropped: positive per-batch constant, ordering-invariant
        s_sim[p0] = s_cd[p0] / fmaxf(sqrtf(hadd2(nr0)), 1e-12f);
        s_sim[p1] = s_cd[p1] / fmaxf(sqrtf(hadd2(nr1)), 1e-12f);
        s_mask[p0] = 1.0f; s_mask[p1] = 1.0f;
    }
    __syncthreads();

    if (tid < 32) {
        for (int k = 0; k < NOCC; ++k) {
            float best = 3.4e38f; int bi = NP;
#pragma unroll
            for (int q = 0; q < NP / 32; ++q) {
                int idx = tid + q * 32;
                float v = s_sim[idx];
                if (v < best || (v == best && idx < bi)) { best = v; bi = idx; }
            }
#pragma unroll
            for (int off = 16; off; off >>= 1) {
                float ov = __shfl_down_sync(0xffffffffu, best, off);
                int   oi = __shfl_down_sync(0xffffffffu, bi, off);
                if (ov < best || (ov == best && oi < bi)) { best = ov; bi = oi; }
            }
            bi = __shfl_sync(0xffffffffu, bi, 0);
            if (tid == 0) { s_sim[bi] = 3.4e38f; s_mask[bi] = 0.0f; }
            __syncwarp();
        }
    }
    __syncthreads();

    {
        const int p = tid;
        const float mk = s_mask[p];
        float tv[NG];
        float m = -3.4e38f;
#pragma unroll
        for (int g = 0; g < NG; ++g) {
            tv[g] = s_sc[g * NP + p] * 10.0f;
            m = fmaxf(m, tv[g]);
        }
        float ssum = 0.f;
#pragma unroll
        for (int g = 0; g < NG; ++g) { tv[g] = __expf(tv[g] - m); ssum += tv[g]; }
        const float inv = 1.0f / ssum;
        float* oat = out + (size_t)NB * NGC * DD + (size_t)b * NG * NP;
#pragma unroll
        for (int g = 0; g < NG; ++g) {
            float a = tv[g] * inv;
            oat[g * NP + p] = (mk != 0.f) ? a : (1.0f / 17.0f);
            g_scores[((size_t)b * NG + g) * NP + p] = (mk != 0.f) ? a : 0.f;
        }
    }
}

// ======================= K3: group features + cls =========================
// Flat grid 384, block 256, 3 CTAs/SM. Batches walked in REVERSE with the 3
// column-slices of a batch adjacent: first wave reads x still L2-resident
// from K1's tail. Warp-private cp.async double-buffered tiles (R10 mainloop).
#define K3_TP 16
#define K3_NT (NP / K3_TP)            // 36
#define WT_FLOATS (K3_TP * 32)        // 512 floats = 2 KB per buffer
#define K3_OFF_X (NG * NP)            // 9792
#define K3_SMEM_FLOATS (K3_OFF_X + 8 * 2 * WT_FLOATS)   // 17984 floats = 71936 B

extern __shared__ float sm3[];

__global__ void __launch_bounds__(256, 3)
k3_features(const float* __restrict__ x, float* __restrict__ out) {
    const int cid = blockIdx.x;
    const int b   = NB - 1 - cid / 3;       // reverse batch order (L2 reuse)
    const int y   = cid % 3;                // column slice
    const int tid = threadIdx.x;
    const int w   = tid >> 5, ln = tid & 31;
    const int d   = y * 256 + tid;
    float* s_at = sm3;
    float* wt0  = sm3 + K3_OFF_X + w * 2 * WT_FLOATS;

    const size_t xb = (size_t)b * NTOK * DD;
    const float* xsrc = x + xb + DD + y * 256 + w * 32;   // patch 0

    const uint32_t wt_base = (uint32_t)__cvta_generic_to_shared(wt0);

    // prologue: issue warp tiles 0,1
#pragma unroll
    for (int t = 0; t < 2; ++t) {
        uint32_t dst = wt_base + (uint32_t)t * WT_FLOATS * 4;
        const float* src = xsrc + (size_t)t * K3_TP * DD;
#pragma unroll
        for (int k = 0; k < 4; ++k) {
            int idx = ln + 32 * k;
            int row = idx >> 3, ch = idx & 7;
            cpasync16(dst + (uint32_t)(row * 32 + ch * 4) * 4,
                      src + (size_t)row * DD + ch * 4);
        }
        asm volatile("cp.async.commit_group;" ::: "memory");
    }

    // stage attn cooperatively
    for (int i = tid; i < NG * NP; i += 256)
        s_at[i] = g_scores[(size_t)b * NG * NP + i];
    __syncthreads();   // attn visible to all warps

    ull acc[NG];
#pragma unroll
    for (int g = 0; g < NG; ++g) acc[g] = 0ull;

    for (int t = 0; t < K3_NT; ++t) {
        asm volatile("cp.async.wait_group 1;" ::: "memory");
        __syncwarp();
        const float* xt  = wt0 + (t & 1) * WT_FLOATS;
        const float* at0 = s_at + t * K3_TP;
#pragma unroll
        for (int q = 0; q < K3_TP / 4; ++q) {
            float c0 = xt[(4 * q + 0) * 32 + ln];
            float c1 = xt[(4 * q + 1) * 32 + ln];
            float c2 = xt[(4 * q + 2) * 32 + ln];
            float c3 = xt[(4 * q + 3) * 32 + ln];
            ull x01 = pk2(c0, c1), x23 = pk2(c2, c3);
            const float* ap = at0 + 4 * q;
#pragma unroll
            for (int g = 0; g < NG; ++g) {
                ulonglong2 at = *reinterpret_cast<const ulonglong2*>(ap + g * NP);
                fma2(acc[g], x01, at.x);
                fma2(acc[g], x23, at.y);
            }
        }
        __syncwarp();
        if (t + 2 < K3_NT) {
            uint32_t dst = wt_base + (uint32_t)(t & 1) * WT_FLOATS * 4;
            const float* src = xsrc + (size_t)(t + 2) * K3_TP * DD;
#pragma unroll
            for (int k = 0; k < 4; ++k) {
                int idx = ln + 32 * k;
                int row = idx >> 3, ch = idx & 7;
                cpasync16(dst + (uint32_t)(row * 32 + ch * 4) * 4,
                          src + (size_t)row * DD + ch * 4);
            }
        }
        asm volatile("cp.async.commit_group;" ::: "memory");
    }

    float* ob = out + (size_t)b * NGC * DD;
    ob[d] = x[xb + d];                        // feats[b][0][d] = cls
#pragma unroll
    for (int g = 0; g < NG; ++g)
        ob[(size_t)(1 + g) * DD + d] = hadd2(acc[g]);
}

extern "C" void kernel_launch(void* const* d_in, const int* in_sizes, int n_in,
                              void* d_out, int out_size) {
    const float* x  = (const float*)d_in[0];
    const float* gw = (const float*)d_in[1];
    float* out = (float*)d_out;

    static bool inited = false;
    if (!inited) {
        cudaFuncSetAttribute(k1_scores, cudaFuncAttributeMaxDynamicSharedMemorySize,
                             K1_SMEM_FLOATS * 4);
        cudaFuncSetAttribute(k3_features, cudaFuncAttributeMaxDynamicSharedMemorySize,
                             K3_SMEM_FLOATS * 4);
        inited = true;
    }

    k1_scores<<<NB, K1_THREADS, K1_SMEM_FLOATS * 4>>>(x, gw, out);
    k3_features<<<3 * NB, 256, K3_SMEM_FLOATS * 4>>>(x, out);
}

// round 15
// speedup vs baseline: 1.1821x; 1.0530x over previous
#include <cuda_runtime.h>
#include <cstdint>
#include <math.h>

#define NB 128
#define NTOK 577
#define NP 576
#define DD 768
#define NG 17
#define NGC 18          // 17 groups + cls row
#define NOCC 10

typedef unsigned long long ull;

// ---- packed f32x2 helpers (sm_103a) ----
__device__ __forceinline__ ull pk2(float a, float b) {
    ull r; asm("mov.b64 %0, {%1,%2};" : "=l"(r) : "f"(a), "f"(b)); return r;
}
__device__ __forceinline__ void fma2(ull &acc, ull a, ull b) {
    asm("fma.rn.f32x2 %0, %1, %2, %0;" : "+l"(acc) : "l"(a), "l"(b));
}
__device__ __forceinline__ float hadd2(ull a) {
    return __uint_as_float((unsigned)a) + __uint_as_float((unsigned)(a >> 32));
}
__device__ __forceinline__ void cpasync16(uint32_t dst, const void* src) {
    asm volatile("cp.async.cg.shared.global [%0], [%1], 16;"
                 :: "r"(dst), "l"(src) : "memory");
}

// scratch (device global; no allocation). Holds MASKED attn after K1.
__device__ float g_scores[(size_t)NB * NG * NP];

// ================= K1: scores + sim + topk + softmax + attn ===============
// (unchanged from R7 — proven)
#define K1_THREADS 576
#define TILE_D 32
#define NT (DD / TILE_D)            // 24
#define PITCH 36                    // floats/row: conflict-free LDS.128
#define TILE_FLOATS (32 * PITCH)    // 1152
#define WPITCH 772                  // W row pitch: 9*772*4 % 128 = 16 (bank-split)
#define OFF_W  (18 * 2 * TILE_FLOATS)          // 41472
#define OFF_CD (OFF_W + NGC * WPITCH)          // 55368
#define K1_SMEM_FLOATS (OFF_CD + NP)           // 55944 floats = 223776 B

extern __shared__ float sm1[];

__global__ void __launch_bounds__(K1_THREADS, 1)
k1_scores(const float* __restrict__ x, const float* __restrict__ gw,
          float* __restrict__ out) {
    const int b   = blockIdx.x;
    const int tid = threadIdx.x;
    const int w   = tid >> 5, ln = tid & 31;
    const int li  = ln & 15,  h  = ln >> 4;
    float* s_w  = sm1 + OFF_W;
    float* s_cd = sm1 + OFF_CD;

    const size_t xb = (size_t)b * NTOK * DD;

    for (int i = tid; i < DD * NG; i += K1_THREADS) {
        int d = i / NG, g = i % NG;
        s_w[g * WPITCH + d] = gw[i];
    }
    for (int i = tid; i < DD; i += K1_THREADS) s_w[NG * WPITCH + i] = x[xb + i];

    const uint32_t smem_base = (uint32_t)__cvta_generic_to_shared(sm1);
    const uint32_t buf0 = smem_base + (uint32_t)(w * 2) * TILE_FLOATS * 4;
    const uint32_t buf1 = buf0 + TILE_FLOATS * 4;
    const float* xrow = x + xb + DD + (size_t)(w * 32) * DD;

#pragma unroll
    for (int t = 0; t < 2; ++t) {
        uint32_t dst = t ? buf1 : buf0;
        const float* src = xrow + t * TILE_D;
#pragma unroll
        for (int k = 0; k < 8; ++k) {
            int idx = ln + 32 * k;
            int row = idx >> 3, ch = idx & 7;
            cpasync16(dst + (uint32_t)(row * PITCH + ch * 4) * 4,
                      src + (size_t)row * DD + ch * 4);
        }
        asm volatile("cp.async.commit_group;" ::: "memory");
    }
    __syncthreads();

    ull a0[9], a1[9], nr0 = 0, nr1 = 0;
#pragma unroll
    for (int g = 0; g < 9; ++g) { a0[g] = 0; a1[g] = 0; }

    const float* wbase = s_w + h * 9 * WPITCH;

    for (int t = 0; t < NT; ++t) {
        asm volatile("cp.async.wait_group 1;" ::: "memory");
        __syncwarp();
        const float* xt  = sm1 + (size_t)(w * 2 + (t & 1)) * TILE_FLOATS;
        const float* wd0 = wbase + t * TILE_D;
#pragma unroll
        for (int blk = 0; blk < 8; ++blk) {
            ulonglong2 xv0 = *reinterpret_cast<const ulonglong2*>(
                xt + li * PITCH + blk * 4);
            ulonglong2 xv1 = *reinterpret_cast<const ulonglong2*>(
                xt + (li + 16) * PITCH + blk * 4);
            const float* wdb = wd0 + blk * 4;
#pragma unroll
            for (int gi = 0; gi < 9; ++gi) {
                ulonglong2 wv = *reinterpret_cast<const ulonglong2*>(wdb + gi * WPITCH);
                fma2(a0[gi], xv0.x, wv.x); fma2(a0[gi], xv0.y, wv.y);
                fma2(a1[gi], xv1.x, wv.x); fma2(a1[gi], xv1.y, wv.y);
            }
            fma2(nr0, xv0.x, xv0.x); fma2(nr0, xv0.y, xv0.y);
            fma2(nr1, xv1.x, xv1.x); fma2(nr1, xv1.y, xv1.y);
        }
        __syncwarp();
        if (t + 2 < NT) {
            uint32_t dst = (t & 1) ? buf1 : buf0;
            const float* src = xrow + (t + 2) * TILE_D;
#pragma unroll
            for (int k = 0; k < 8; ++k) {
                int idx = ln + 32 * k;
                int row = idx >> 3, ch = idx & 7;
                cpasync16(dst + (uint32_t)(row * PITCH + ch * 4) * 4,
                          src + (size_t)row * DD + ch * 4);
            }
        }
        asm volatile("cp.async.commit_group;" ::: "memory");
    }

    // epilogue: scores -> smem (tile region dead)
    __syncthreads();
    float* s_sc   = sm1;
    float* s_sim  = sm1 + NG * NP;
    float* s_mask = s_sim + NP;

    const int p0 = w * 32 + li, p1 = p0 + 16;
#pragma unroll
    for (int gi = 0; gi < 9; ++gi) {
        int g = h * 9 + gi;
        float v0 = hadd2(a0[gi]), v1 = hadd2(a1[gi]);
        if (g < NG) {
            s_sc[g * NP + p0] = v0;
            s_sc[g * NP + p1] = v1;
        } else {
            s_cd[p0] = v0;
            s_cd[p1] = v1;
        }
    }
    __syncthreads();
    if (h == 0) {
        // cls-norm factor dropped: positive per-batch constant, ordering-invariant
        s_sim[p0] = s_cd[p0] / fmaxf(sqrtf(hadd2(nr0)), 1e-12f);
        s_sim[p1] = s_cd[p1] / fmaxf(sqrtf(hadd2(nr1)), 1e-12f);
        s_mask[p0] = 1.0f; s_mask[p1] = 1.0f;
    }
    __syncthreads();

    if (tid < 32) {
        for (int k = 0; k < NOCC; ++k) {
            float best = 3.4e38f; int bi = NP;
#pragma unroll
            for (int q = 0; q < NP / 32; ++q) {
                int idx = tid + q * 32;
                float v = s_sim[idx];
                if (v < best || (v == best && idx < bi)) { best = v; bi = idx; }
            }
#pragma unroll
            for (int off = 16; off; off >>= 1) {
                float ov = __shfl_down_sync(0xffffffffu, best, off);
                int   oi = __shfl_down_sync(0xffffffffu, bi, off);
                if (ov < best || (ov == best && oi < bi)) { best = ov; bi = oi; }
            }
            bi = __shfl_sync(0xffffffffu, bi, 0);
            if (tid == 0) { s_sim[bi] = 3.4e38f; s_mask[bi] = 0.0f; }
            __syncwarp();
        }
    }
    __syncthreads();

    {
        const int p = tid;
        const float mk = s_mask[p];
        float tv[NG];
        float m = -3.4e38f;
#pragma unroll
        for (int g = 0; g < NG; ++g) {
            tv[g] = s_sc[g * NP + p] * 10.0f;
            m = fmaxf(m, tv[g]);
        }
        float ssum = 0.f;
#pragma unroll
        for (int g = 0; g < NG; ++g) { tv[g] = __expf(tv[g] - m); ssum += tv[g]; }
        const float inv = 1.0f / ssum;
        float* oat = out + (size_t)NB * NGC * DD + (size_t)b * NG * NP;
#pragma unroll
        for (int g = 0; g < NG; ++g) {
            float a = tv[g] * inv;
            oat[g * NP + p] = (mk != 0.f) ? a : (1.0f / 17.0f);
            g_scores[((size_t)b * NG + g) * NP + p] = (mk != 0.f) ? a : 0.f;
        }
    }
}

// ======================= K3: group features + cls =========================
// Flat grid 384, block 256, 3 CTAs/SM, reverse batch order (L2 reuse).
// Warp-private cp.async double-buffered row-major x tiles [16p x 32c] (R10).
// Thread (li=ln&15, h=ln>>4): columns li, li+16; groups [9h, 9h+9).
// attn halves separated by a 4-float pad -> half-warp broadcasts bank-disjoint.
// Row 17 of attn = zeros (uniform 9-group loop for h=1).
#define K3_TP 16
#define K3_NT (NP / K3_TP)            // 36
#define WT_FLOATS (K3_TP * 32)        // 512 floats = 2 KB per buffer
#define AT_HB (9 * NP + 4)            // half-block stride (16B bank shift)
#define K3_OFF_X (2 * 9 * NP + 4)     // 10372
#define K3_SMEM_FLOATS (K3_OFF_X + 8 * 2 * WT_FLOATS)   // 18564 fl = 74256 B

extern __shared__ float sm3[];

__global__ void __launch_bounds__(256, 3)
k3_features(const float* __restrict__ x, float* __restrict__ out) {
    const int cid = blockIdx.x;
    const int b   = NB - 1 - cid / 3;       // reverse batch order (L2 reuse)
    const int y   = cid % 3;                // column slice
    const int tid = threadIdx.x;
    const int w   = tid >> 5, ln = tid & 31;
    const int li  = ln & 15,  h  = ln >> 4;
    float* s_at = sm3;
    float* wt0  = sm3 + K3_OFF_X + w * 2 * WT_FLOATS;

    const size_t xb = (size_t)b * NTOK * DD;
    const float* xsrc = x + xb + DD + y * 256 + w * 32;   // patch 0

    const uint32_t wt_base = (uint32_t)__cvta_generic_to_shared(wt0);

    // prologue: issue warp tiles 0,1 (R10 pattern, 16B cp.async coalesced)
#pragma unroll
    for (int t = 0; t < 2; ++t) {
        uint32_t dst = wt_base + (uint32_t)t * WT_FLOATS * 4;
        const float* src = xsrc + (size_t)t * K3_TP * DD;
#pragma unroll
        for (int k = 0; k < 4; ++k) {
            int idx = ln + 32 * k;
            int row = idx >> 3, ch = idx & 7;
            cpasync16(dst + (uint32_t)(row * 32 + ch * 4) * 4,
                      src + (size_t)row * DD + ch * 4);
        }
        asm volatile("cp.async.commit_group;" ::: "memory");
    }

    // stage attn: rows 0-8 at [0), rows 9-16 at [AT_HB), row 17 zeros
    for (int i = tid; i < NG * NP; i += 256) {
        int g = i / NP, j = i - g * NP;
        float v = g_scores[(size_t)b * NG * NP + i];
        s_at[(g < 9 ? g * NP : AT_HB + (g - 9) * NP) + j] = v;
    }
    for (int j = tid; j < NP; j += 256)
        s_at[AT_HB + 8 * NP + j] = 0.0f;      // zero row (g=17)
    __syncthreads();

    ull acc0[9], acc1[9];
#pragma unroll
    for (int g = 0; g < 9; ++g) { acc0[g] = 0; acc1[g] = 0; }

    const float* athalf = s_at + h * AT_HB;

    for (int t = 0; t < K3_NT; ++t) {
        asm volatile("cp.async.wait_group 1;" ::: "memory");
        __syncwarp();
        const float* xt  = wt0 + (t & 1) * WT_FLOATS;
        const float* at0 = athalf + t * K3_TP;
#pragma unroll
        for (int q = 0; q < K3_TP / 4; ++q) {
            const float* xq = xt + 4 * q * 32;
            float c00 = xq[0 * 32 + li],      c01 = xq[1 * 32 + li];
            float c02 = xq[2 * 32 + li],      c03 = xq[3 * 32 + li];
            float c10 = xq[0 * 32 + li + 16], c11 = xq[1 * 32 + li + 16];
            float c12 = xq[2 * 32 + li + 16], c13 = xq[3 * 32 + li + 16];
            ull x01c0 = pk2(c00, c01), x23c0 = pk2(c02, c03);
            ull x01c1 = pk2(c10, c11), x23c1 = pk2(c12, c13);
            const float* ap = at0 + 4 * q;
#pragma unroll
            for (int gi = 0; gi < 9; ++gi) {
                ulonglong2 at = *reinterpret_cast<const ulonglong2*>(ap + gi * NP);
                fma2(acc0[gi], x01c0, at.x); fma2(acc0[gi], x23c0, at.y);
                fma2(acc1[gi], x01c1, at.x); fma2(acc1[gi], x23c1, at.y);
            }
        }
        __syncwarp();
        if (t + 2 < K3_NT) {
            uint32_t dst = wt_base + (uint32_t)(t & 1) * WT_FLOATS * 4;
            const float* src = xsrc + (size_t)(t + 2) * K3_TP * DD;
#pragma unroll
            for (int k = 0; k < 4; ++k) {
                int idx = ln + 32 * k;
                int row = idx >> 3, ch = idx & 7;
                cpasync16(dst + (uint32_t)(row * 32 + ch * 4) * 4,
                          src + (size_t)row * DD + ch * 4);
            }
        }
        asm volatile("cp.async.commit_group;" ::: "memory");
    }

    const int d0 = y * 256 + w * 32 + li, d1 = d0 + 16;
    float* ob = out + (size_t)b * NGC * DD;
    if (h == 0) {
        ob[d0] = x[xb + d0];                  // feats[b][0][*] = cls
        ob[d1] = x[xb + d1];
#pragma unroll
        for (int gi = 0; gi < 9; ++gi) {      // groups 0..8
            ob[(size_t)(1 + gi) * DD + d0] = hadd2(acc0[gi]);
            ob[(size_t)(1 + gi) * DD + d1] = hadd2(acc1[gi]);
        }
    } else {
#pragma unroll
        for (int gi = 0; gi < 8; ++gi) {      // groups 9..16 (gi=8 is zero row)
            ob[(size_t)(1 + 9 + gi) * DD + d0] = hadd2(acc0[gi]);
            ob[(size_t)(1 + 9 + gi) * DD + d1] = hadd2(acc1[gi]);
        }
    }
}

extern "C" void kernel_launch(void* const* d_in, const int* in_sizes, int n_in,
                              void* d_out, int out_size) {
    const float* x  = (const float*)d_in[0];
    const float* gw = (const float*)d_in[1];
    float* out = (float*)d_out;

    static bool inited = false;
    if (!inited) {
        cudaFuncSetAttribute(k1_scores, cudaFuncAttributeMaxDynamicSharedMemorySize,
                             K1_SMEM_FLOATS * 4);
        cudaFuncSetAttribute(k3_features, cudaFuncAttributeMaxDynamicSharedMemorySize,
                             K3_SMEM_FLOATS * 4);
        inited = true;
    }

    k1_scores<<<NB, K1_THREADS, K1_SMEM_FLOATS * 4>>>(x, gw, out);
    k3_features<<<3 * NB, 256, K3_SMEM_FLOATS * 4>>>(x, out);
}